// round 11
// baseline (speedup 1.0000x reference)
#include <cuda_runtime.h>
#include <cuda_bf16.h>
#include <cstdint>

// ---------------------------------------------------------------------------
// BarrierNet — mma.sync split-bf16, v11: 32x32 warp tiles.
//   CTA = 512 threads, 512 rows, four 128-row phases. 2 CTAs/SM = 32 warps.
//   Phase A : all 16 warps, layer1 FFMA2 (j-pairs), silu, split, STS swizzled.
//   MMA     : warps 0-7 only, each 32 rows x 32 cols (B frags amortized 2x),
//             3-pass split-bf16 (AhiBhi + AloBhi + AhiBlo), fp32 acc.
//   Heads   : partials in MMA warps, quad shfl-reduce, tig-select row write.
//   CBF     : warps 8-11 (tid 256-383) after the barrier.
// ---------------------------------------------------------------------------

typedef unsigned long long u64;
typedef unsigned int u32;

#define SM_XHI   0        // 128 rows x 256B
#define SM_XLO   32768
#define SM_WHI   65536    // 64 n x 256B
#define SM_WLO   81920
#define SM_W1P   98304    // u64[640]  W1 (j,j+1) pairs
#define SM_B1P   103424   // u64[64]
#define SM_B2    103936   // f32[64]
#define SM_W31   104192   // f32[64]
#define SM_W32   104448   // f32[32]
#define SM_SCAL  104576   // f32[4]
#define SM_U01   104592   // float2[128]
#define SM_AW    105616   // float[128]
#define SMEM_BYTES 106128

static __device__ __forceinline__ u32 smem_u32(const void* p) {
    u32 a;
    asm("{ .reg .u64 t; cvta.to.shared.u64 t, %1; cvt.u32.u64 %0, t; }"
        : "=r"(a) : "l"(p));
    return a;
}
static __device__ __forceinline__ u64 pk2(float lo, float hi) {
    u64 r; asm("mov.b64 %0, {%1, %2};" : "=l"(r) : "f"(lo), "f"(hi)); return r;
}
static __device__ __forceinline__ void upk2(u64 v, float& lo, float& hi) {
    asm("mov.b64 {%0, %1}, %2;" : "=f"(lo), "=f"(hi) : "l"(v));
}
static __device__ __forceinline__ u64 fma2(u64 a, u64 b, u64 c) {
    u64 d; asm("fma.rn.f32x2 %0, %1, %2, %3;" : "=l"(d) : "l"(a), "l"(b), "l"(c)); return d;
}
static __device__ __forceinline__ u64 dup2(float w) { return pk2(w, w); }

static __device__ __forceinline__ float fast_silu(float z) {
    return __fdividef(z, 1.0f + __expf(-z));
}
static __device__ __forceinline__ float fast_sigmoid(float z) {
    return __fdividef(1.0f, 1.0f + __expf(-z));
}
static __device__ __forceinline__ u32 cvt_bf16x2(float hi, float lo) {
    u32 d; asm("cvt.rn.bf16x2.f32 %0, %1, %2;" : "=r"(d) : "f"(hi), "f"(lo));
    return d;
}
// hi/lo split of two floats -> packed hi u32, packed lo u32 (lower = s0)
static __device__ __forceinline__ void split2(float s0, float s1, u32& h, u32& l) {
    h = cvt_bf16x2(s1, s0);
    float f0 = __uint_as_float(h << 16);
    float f1 = __uint_as_float(h & 0xFFFF0000u);
    l = cvt_bf16x2(s1 - f1, s0 - f0);
}

static __device__ __forceinline__ void ldsm4(u32* r, u32 addr) {
    asm volatile("ldmatrix.sync.aligned.m8n8.x4.shared.b16 {%0,%1,%2,%3}, [%4];"
        : "=r"(r[0]), "=r"(r[1]), "=r"(r[2]), "=r"(r[3]) : "r"(addr));
}
static __device__ __forceinline__ void mma_bf16(float* d, const u32* a, u32 b0, u32 b1) {
    asm volatile("mma.sync.aligned.m16n8k16.row.col.f32.bf16.bf16.f32 "
        "{%0,%1,%2,%3}, {%4,%5,%6,%7}, {%8,%9}, {%0,%1,%2,%3};"
        : "+f"(d[0]), "+f"(d[1]), "+f"(d[2]), "+f"(d[3])
        : "r"(a[0]), "r"(a[1]), "r"(a[2]), "r"(a[3]), "r"(b0), "r"(b1));
}

__global__ void __launch_bounds__(512, 2)
barriernet_kernel(const float* __restrict__ obs,
                  const float* __restrict__ W1,  const float* __restrict__ b1,
                  const float* __restrict__ W21, const float* __restrict__ b21,
                  const float* __restrict__ W22, const float* __restrict__ b22,
                  const float* __restrict__ W31, const float* __restrict__ b31,
                  const float* __restrict__ W32, const float* __restrict__ b32,
                  float* __restrict__ out, int B)
{
    extern __shared__ char smc[];
    const u32 smb = smem_u32(smc);
    const int tid = threadIdx.x;

    u64*    w1p  = reinterpret_cast<u64*>(smc + SM_W1P);
    u64*    b1p  = reinterpret_cast<u64*>(smc + SM_B1P);
    float*  b2f  = reinterpret_cast<float*>(smc + SM_B2);
    float*  w31f = reinterpret_cast<float*>(smc + SM_W31);
    float*  w32f = reinterpret_cast<float*>(smc + SM_W32);
    float*  scal = reinterpret_cast<float*>(smc + SM_SCAL);
    float2* u01  = reinterpret_cast<float2*>(smc + SM_U01);
    float*  awb  = reinterpret_cast<float*>(smc + SM_AW);

    // ------------------------------ staging ------------------------------
    for (int i = tid; i < 640; i += 512) {
        int jp = i / 10, f = i - jp * 10;
        w1p[i] = pk2(W1[(2 * jp) * 10 + f], W1[(2 * jp + 1) * 10 + f]);
    }
    if (tid < 64) {
        b1p[tid]  = pk2(b1[2 * tid], b1[2 * tid + 1]);
        b2f[tid]  = (tid < 32) ? b21[tid] : b22[tid - 32];
        w31f[tid] = W31[tid];                       // [2][32] row-major
    }
    if (tid < 32) w32f[tid] = W32[tid];
    if (tid == 0) { scal[0] = b31[0]; scal[1] = b31[1]; scal[2] = b32[0]; }

    for (int i = tid; i < 4096; i += 512) {
        int n = i >> 6, kp = i & 63;                // elems k = 2kp, 2kp+1
        const float* src = (n < 32) ? (W21 + n * 128 + 2 * kp)
                                    : (W22 + (n - 32) * 128 + 2 * kp);
        float2 w = *reinterpret_cast<const float2*>(src);
        u32 h, l;
        split2(w.x, w.y, h, l);
        u32 off = (u32)(n * 256) + (((u32)(4 * kp)) ^ ((u32)(n & 7) << 4));
        *reinterpret_cast<u32*>(smc + SM_WHI + off) = h;
        *reinterpret_cast<u32*>(smc + SM_WLO + off) = l;
    }
    __syncthreads();

    const long long row_base = (long long)blockIdx.x * 512;

    // -------- phase-A mapping: row = tid&127, j-group = tid>>7 --------
    const int prow = tid & 127;
    const int jq   = tid >> 7;          // 16 j-pairs starting at jq*16

    // -------- mma mapping (warps 0-7): 32 rows x 32 cols --------
    const int wid = tid >> 5, lane = tid & 31;
    const int gid = lane >> 2, tig = lane & 3;
    const int g8  = lane >> 3, r8 = lane & 7;
    const int mg  = wid & 3;            // m-group: rows mg*32 .. mg*32+31
    const int nh  = wid >> 2;           // n-half (0: cols 0-31 = u, 1: 32-63 = alpha)
    const u32 swz    = (u32)r8 << 4;
    const u32 a_koff = (u32)((g8 >> 1) << 4);
    const int arow0  = mg * 32 + ((g8 & 1) << 3) + r8;       // msub 0
    const u32 aH0 = smb + SM_XHI + (u32)arow0 * 256;
    const u32 aH1 = aH0 + 16 * 256;                          // msub 1
    const u32 aL0 = smb + SM_XLO + (u32)arow0 * 256;
    const u32 aL1 = aL0 + 16 * 256;
    const u32 b_noff = (u32)(((g8 >> 1) << 3) + r8);
    const u32 b_koff = (u32)((g8 & 1) << 4);
    u32 bHb[2], bLb[2];
    #pragma unroll
    for (int g = 0; g < 2; g++) {
        u32 n = (u32)(nh * 32 + g * 16) + b_noff;
        bHb[g] = smb + SM_WHI + n * 256;
        bLb[g] = smb + SM_WLO + n * 256;
    }

    #pragma unroll 1
    for (int ph = 0; ph < 4; ph++) {
        // ======================= Phase A (128 rows, all warps) =======================
        {
            const long long grow = row_base + ph * 128 + prow;
            u64 od[10];
            if (grow < B) {
                const float2* q = reinterpret_cast<const float2*>(obs + grow * 10);
                #pragma unroll
                for (int f = 0; f < 5; f++) {
                    float2 v = q[f];
                    od[2 * f]     = dup2(v.x);
                    od[2 * f + 1] = dup2(v.y);
                }
            } else {
                #pragma unroll
                for (int f = 0; f < 10; f++) od[f] = 0ull;
            }
            const u32 swr = ((u32)(prow & 7)) << 4;
            #pragma unroll 1
            for (int blk = 0; blk < 4; blk++) {
                u32 hi[4], lo[4];
                #pragma unroll
                for (int q = 0; q < 4; q++) {
                    const int jp = jq * 16 + blk * 4 + q;
                    const ulonglong2* wv =
                        reinterpret_cast<const ulonglong2*>(w1p + jp * 10);
                    ulonglong2 w01 = wv[0], w23 = wv[1], w45 = wv[2],
                               w67 = wv[3], w89 = wv[4];
                    u64 z = b1p[jp];
                    z = fma2(od[0], w01.x, z); z = fma2(od[1], w01.y, z);
                    z = fma2(od[2], w23.x, z); z = fma2(od[3], w23.y, z);
                    z = fma2(od[4], w45.x, z); z = fma2(od[5], w45.y, z);
                    z = fma2(od[6], w67.x, z); z = fma2(od[7], w67.y, z);
                    z = fma2(od[8], w89.x, z); z = fma2(od[9], w89.y, z);
                    float z0, z1; upk2(z, z0, z1);
                    split2(fast_silu(z0), fast_silu(z1), hi[q], lo[q]);
                }
                const u32 kb  = (u32)(jq * 64 + blk * 16);
                const u32 off = (u32)prow * 256 + (kb ^ swr);
                *reinterpret_cast<uint4*>(smc + SM_XHI + off) =
                    make_uint4(hi[0], hi[1], hi[2], hi[3]);
                *reinterpret_cast<uint4*>(smc + SM_XLO + off) =
                    make_uint4(lo[0], lo[1], lo[2], lo[3]);
            }
        }
        __syncthreads();

        // ======================= MMA: warps 0-7, 32r x 32c =======================
        if (wid < 8) {
            float acc[2][4][4];
            #pragma unroll
            for (int m = 0; m < 2; m++)
                #pragma unroll
                for (int nt = 0; nt < 4; nt++)
                    #pragma unroll
                    for (int c = 0; c < 4; c++) acc[m][nt][c] = 0.f;

            #pragma unroll 1
            for (int ks = 0; ks < 8; ks++) {
                const u32 kbyte = (u32)(32 * ks);
                const u32 ka = (kbyte + a_koff) ^ swz;
                const u32 kb = (kbyte + b_koff) ^ swz;
                u32 ah0[4], ah1[4], bf0[4], bf1[4], al[4];
                // pass 1: A-hi x B-hi
                ldsm4(bf0, bHb[0] + kb);
                ldsm4(bf1, bHb[1] + kb);
                ldsm4(ah0, aH0 + ka);
                ldsm4(ah1, aH1 + ka);
                #pragma unroll
                for (int nt = 0; nt < 4; nt++) {
                    u32 b0 = (nt < 2 ? bf0 : bf1)[(nt & 1) * 2];
                    u32 b1v = (nt < 2 ? bf0 : bf1)[(nt & 1) * 2 + 1];
                    mma_bf16(acc[0][nt], ah0, b0, b1v);
                    mma_bf16(acc[1][nt], ah1, b0, b1v);
                }
                // pass 2: A-lo x B-hi
                ldsm4(al, aL0 + ka);
                #pragma unroll
                for (int nt = 0; nt < 4; nt++) {
                    u32 b0 = (nt < 2 ? bf0 : bf1)[(nt & 1) * 2];
                    u32 b1v = (nt < 2 ? bf0 : bf1)[(nt & 1) * 2 + 1];
                    mma_bf16(acc[0][nt], al, b0, b1v);
                }
                ldsm4(al, aL1 + ka);
                #pragma unroll
                for (int nt = 0; nt < 4; nt++) {
                    u32 b0 = (nt < 2 ? bf0 : bf1)[(nt & 1) * 2];
                    u32 b1v = (nt < 2 ? bf0 : bf1)[(nt & 1) * 2 + 1];
                    mma_bf16(acc[1][nt], al, b0, b1v);
                }
                // pass 3: A-hi x B-lo
                ldsm4(bf0, bLb[0] + kb);
                ldsm4(bf1, bLb[1] + kb);
                #pragma unroll
                for (int nt = 0; nt < 4; nt++) {
                    u32 b0 = (nt < 2 ? bf0 : bf1)[(nt & 1) * 2];
                    u32 b1v = (nt < 2 ? bf0 : bf1)[(nt & 1) * 2 + 1];
                    mma_bf16(acc[0][nt], ah0, b0, b1v);
                    mma_bf16(acc[1][nt], ah1, b0, b1v);
                }
            }

            // ---- heads partials: 4 rows/lane, quad-reduce, tig-select write ----
            float p0[4] = {0.f, 0.f, 0.f, 0.f};   // u0 (nh0) / aw (nh1)
            float p1[4] = {0.f, 0.f, 0.f, 0.f};   // u1 (nh0 only)
            #pragma unroll
            for (int m = 0; m < 2; m++)
                #pragma unroll
                for (int nt = 0; nt < 4; nt++)
                    #pragma unroll
                    for (int c = 0; c < 2; c++) {
                        const int col = nh * 32 + nt * 8 + 2 * tig + c;
                        const float bias = b2f[col];
                        const float vlo = fast_silu(acc[m][nt][c] + bias);     // row i=2m
                        const float vhi = fast_silu(acc[m][nt][2 + c] + bias); // row i=2m+1
                        if (nh == 0) {
                            const float wA = w31f[col], wB = w31f[32 + col];
                            p0[2 * m]     += vlo * wA; p1[2 * m]     += vlo * wB;
                            p0[2 * m + 1] += vhi * wA; p1[2 * m + 1] += vhi * wB;
                        } else {
                            const float wC = w32f[col - 32];
                            p0[2 * m]     += vlo * wC;
                            p0[2 * m + 1] += vhi * wC;
                        }
                    }
            #pragma unroll
            for (int i = 0; i < 4; i++) {
                p0[i] += __shfl_xor_sync(0xFFFFFFFFu, p0[i], 1);
                p0[i] += __shfl_xor_sync(0xFFFFFFFFu, p0[i], 2);
                if (nh == 0) {
                    p1[i] += __shfl_xor_sync(0xFFFFFFFFu, p1[i], 1);
                    p1[i] += __shfl_xor_sync(0xFFFFFFFFu, p1[i], 2);
                }
            }
            // lane (gid, tig) writes row mg*32 + gid + tig*8  (i = tig)
            {
                const int row = mg * 32 + gid + tig * 8;
                const float s0 = (tig == 0) ? p0[0] : (tig == 1) ? p0[1]
                               : (tig == 2) ? p0[2] : p0[3];
                if (nh == 0) {
                    const float s1 = (tig == 0) ? p1[0] : (tig == 1) ? p1[1]
                                   : (tig == 2) ? p1[2] : p1[3];
                    u01[row] = make_float2(s0, s1);
                } else {
                    awb[row] = s0;
                }
            }
        }
        __syncthreads();

        // ======================= CBF + store (warps 8-11) =======================
        if (tid >= 256 && tid < 384) {
            const int r = tid - 256;
            const long long grow = row_base + ph * 128 + r;
            if (grow < B) {
                float2 uv = u01[r];
                const float u0 = uv.x + scal[0];
                const float u1 = uv.y + scal[1];
                const float aw = awb[r] + scal[2];
                const float2* pp = reinterpret_cast<const float2*>(obs + grow * 10 + 6);
                const float2 rv = pp[0], vv = pp[1];
                const float alpha   = 4.0f * fast_sigmoid(aw);
                const float barrier = rv.x * rv.x + rv.y * rv.y - 0.64f;
                const float lf      = -2.0f * (rv.x * vv.x + rv.y * vv.y);
                const float Gx = -2.0f * rv.x, Gy = -2.0f * rv.y;
                const float hh   = lf + alpha * barrier;
                const float gg   = Gx * Gx + Gy * Gy;
                const float viol = Gx * u0 + Gy * u1 - hh;
                const float lam  = (gg > 0.0f)
                    ? __fdividef(fmaxf(viol, 0.0f), fmaxf(gg, 1e-12f))
                    : 0.0f;
                reinterpret_cast<float2*>(out)[grow] =
                    make_float2(u0 - lam * Gx, u1 - lam * Gy);
            }
        }
    }
}

extern "C" void kernel_launch(void* const* d_in, const int* in_sizes, int n_in,
                              void* d_out, int out_size)
{
    const float* obs = (const float*)d_in[0];
    const float* W1  = (const float*)d_in[1];
    const float* b1  = (const float*)d_in[2];
    const float* W21 = (const float*)d_in[3];
    const float* b21 = (const float*)d_in[4];
    const float* W22 = (const float*)d_in[5];
    const float* b22 = (const float*)d_in[6];
    const float* W31 = (const float*)d_in[7];
    const float* b31 = (const float*)d_in[8];
    const float* W32 = (const float*)d_in[9];
    const float* b32 = (const float*)d_in[10];
    float* out = (float*)d_out;

    int B = in_sizes[0] / 10;

    cudaFuncSetAttribute(barriernet_kernel,
                         cudaFuncAttributeMaxDynamicSharedMemorySize, SMEM_BYTES);

    int blocks = (B + 511) / 512;
    barriernet_kernel<<<blocks, 512, SMEM_BYTES>>>(
        obs, W1, b1, W21, b21, W22, b22, W31, b31, W32, b32, out, B);
}

// round 12
// speedup vs baseline: 1.1744x; 1.1744x over previous
#include <cuda_runtime.h>
#include <cuda_fp16.h>
#include <cstdint>

// ---------------------------------------------------------------------------
// BarrierNet — mma.sync fp16 (single-A, split-B), v12.
//   CTA = 512 threads, 512 rows, four 128-row phases. 2 CTAs/SM.
//   Phase A : layer1 fp32 FFMA2, silu, single cvt to fp16x2, STS swizzled.
//   MMA     : warps 0-7, 32r x 32c tiles, 2 passes: A*Bhi + A*Blo, fp32 acc.
//   Heads   : partials in MMA warps, quad shfl-reduce, tig-select write.
//   CBF     : warps 8-11 after the barrier.
// ---------------------------------------------------------------------------

typedef unsigned long long u64;
typedef unsigned int u32;

#define SM_XF    0        // fp16 x [128 rows][128 k]  32768
#define SM_WHI   32768    // fp16 W2_hi [64 n][128 k]  16384
#define SM_WLO   49152    // fp16 W2_lo                16384
#define SM_W1P   65536    // u64[640]  W1 (j,j+1) pairs 5120
#define SM_B1P   70656    // u64[64]   512
#define SM_B2    71168    // f32[64]   256
#define SM_W31   71424    // f32[64]   256
#define SM_W32   71680    // f32[32]   128
#define SM_SCAL  71808    // f32[4]
#define SM_U01   71824    // float2[128] 1024
#define SM_AW    72848    // f32[128]    512
#define SMEM_BYTES 73360

static __device__ __forceinline__ u32 smem_u32(const void* p) {
    u32 a;
    asm("{ .reg .u64 t; cvta.to.shared.u64 t, %1; cvt.u32.u64 %0, t; }"
        : "=r"(a) : "l"(p));
    return a;
}
static __device__ __forceinline__ u64 pk2(float lo, float hi) {
    u64 r; asm("mov.b64 %0, {%1, %2};" : "=l"(r) : "f"(lo), "f"(hi)); return r;
}
static __device__ __forceinline__ void upk2(u64 v, float& lo, float& hi) {
    asm("mov.b64 {%0, %1}, %2;" : "=f"(lo), "=f"(hi) : "l"(v));
}
static __device__ __forceinline__ u64 fma2(u64 a, u64 b, u64 c) {
    u64 d; asm("fma.rn.f32x2 %0, %1, %2, %3;" : "=l"(d) : "l"(a), "l"(b), "l"(c)); return d;
}
static __device__ __forceinline__ u64 dup2(float w) { return pk2(w, w); }

static __device__ __forceinline__ float fast_silu(float z) {
    return __fdividef(z, 1.0f + __expf(-z));
}
static __device__ __forceinline__ float fast_sigmoid(float z) {
    return __fdividef(1.0f, 1.0f + __expf(-z));
}
// pack two floats to fp16x2 (lower 16 bits = s0)
static __device__ __forceinline__ u32 cvt_f16x2(float s1, float s0) {
    u32 d; asm("cvt.rn.f16x2.f32 %0, %1, %2;" : "=r"(d) : "f"(s1), "f"(s0));
    return d;
}
// fp16 hi/lo split of two floats (staging only)
static __device__ __forceinline__ void split2h(float s0, float s1, u32& h, u32& l) {
    h = cvt_f16x2(s1, s0);
    __half2 hv = *reinterpret_cast<__half2*>(&h);
    float f0 = __low2float(hv), f1 = __high2float(hv);
    l = cvt_f16x2(s1 - f1, s0 - f0);
}
static __device__ __forceinline__ void ldsm4(u32* r, u32 addr) {
    asm volatile("ldmatrix.sync.aligned.m8n8.x4.shared.b16 {%0,%1,%2,%3}, [%4];"
        : "=r"(r[0]), "=r"(r[1]), "=r"(r[2]), "=r"(r[3]) : "r"(addr));
}
static __device__ __forceinline__ void mma_f16(float* d, const u32* a, u32 b0, u32 b1) {
    asm volatile("mma.sync.aligned.m16n8k16.row.col.f32.f16.f16.f32 "
        "{%0,%1,%2,%3}, {%4,%5,%6,%7}, {%8,%9}, {%0,%1,%2,%3};"
        : "+f"(d[0]), "+f"(d[1]), "+f"(d[2]), "+f"(d[3])
        : "r"(a[0]), "r"(a[1]), "r"(a[2]), "r"(a[3]), "r"(b0), "r"(b1));
}

__global__ void __launch_bounds__(512, 2)
barriernet_kernel(const float* __restrict__ obs,
                  const float* __restrict__ W1,  const float* __restrict__ b1,
                  const float* __restrict__ W21, const float* __restrict__ b21,
                  const float* __restrict__ W22, const float* __restrict__ b22,
                  const float* __restrict__ W31, const float* __restrict__ b31,
                  const float* __restrict__ W32, const float* __restrict__ b32,
                  float* __restrict__ out, int B)
{
    extern __shared__ char smc[];
    const u32 smb = smem_u32(smc);
    const int tid = threadIdx.x;

    u64*    w1p  = reinterpret_cast<u64*>(smc + SM_W1P);
    u64*    b1p  = reinterpret_cast<u64*>(smc + SM_B1P);
    float*  b2f  = reinterpret_cast<float*>(smc + SM_B2);
    float*  w31f = reinterpret_cast<float*>(smc + SM_W31);
    float*  w32f = reinterpret_cast<float*>(smc + SM_W32);
    float*  scal = reinterpret_cast<float*>(smc + SM_SCAL);
    float2* u01  = reinterpret_cast<float2*>(smc + SM_U01);
    float*  awb  = reinterpret_cast<float*>(smc + SM_AW);

    // ------------------------------ staging ------------------------------
    for (int i = tid; i < 640; i += 512) {
        int jp = i / 10, f = i - jp * 10;
        w1p[i] = pk2(W1[(2 * jp) * 10 + f], W1[(2 * jp + 1) * 10 + f]);
    }
    if (tid < 64) {
        b1p[tid]  = pk2(b1[2 * tid], b1[2 * tid + 1]);
        b2f[tid]  = (tid < 32) ? b21[tid] : b22[tid - 32];
        w31f[tid] = W31[tid];                       // [2][32] row-major
    }
    if (tid < 32) w32f[tid] = W32[tid];
    if (tid == 0) { scal[0] = b31[0]; scal[1] = b31[1]; scal[2] = b32[0]; }

    // W2 = [W21 ; W22] fp16 hi + residual, [n][k] 256B rows, XOR swizzle
    for (int i = tid; i < 4096; i += 512) {
        int n = i >> 6, kp = i & 63;                // elems k = 2kp, 2kp+1
        const float* src = (n < 32) ? (W21 + n * 128 + 2 * kp)
                                    : (W22 + (n - 32) * 128 + 2 * kp);
        float2 w = *reinterpret_cast<const float2*>(src);
        u32 h, l;
        split2h(w.x, w.y, h, l);
        u32 off = (u32)(n * 256) + (((u32)(4 * kp)) ^ ((u32)(n & 7) << 4));
        *reinterpret_cast<u32*>(smc + SM_WHI + off) = h;
        *reinterpret_cast<u32*>(smc + SM_WLO + off) = l;
    }
    __syncthreads();

    const long long row_base = (long long)blockIdx.x * 512;

    // -------- phase-A mapping --------
    const int prow = tid & 127;
    const int jq   = tid >> 7;          // 16 j-pairs starting at jq*16

    // -------- mma mapping (warps 0-7): 32 rows x 32 cols --------
    const int wid = tid >> 5, lane = tid & 31;
    const int gid = lane >> 2, tig = lane & 3;
    const int g8  = lane >> 3, r8 = lane & 7;
    const int mg  = wid & 3;            // rows mg*32 .. mg*32+31
    const int nh  = wid >> 2;           // n-half (0: u cols, 1: alpha cols)
    const u32 swz    = (u32)r8 << 4;
    const u32 a_koff = (u32)((g8 >> 1) << 4);
    const int arow0  = mg * 32 + ((g8 & 1) << 3) + r8;
    const u32 aF0 = smb + SM_XF + (u32)arow0 * 256;
    const u32 aF1 = aF0 + 16 * 256;
    const u32 b_noff = (u32)(((g8 >> 1) << 3) + r8);
    const u32 b_koff = (u32)((g8 & 1) << 4);
    u32 bHb[2], bLb[2];
    #pragma unroll
    for (int g = 0; g < 2; g++) {
        u32 n = (u32)(nh * 32 + g * 16) + b_noff;
        bHb[g] = smb + SM_WHI + n * 256;
        bLb[g] = smb + SM_WLO + n * 256;
    }

    #pragma unroll 1
    for (int ph = 0; ph < 4; ph++) {
        // ======================= Phase A (128 rows, all warps) =======================
        {
            const long long grow = row_base + ph * 128 + prow;
            u64 od[10];
            if (grow < B) {
                const float2* q = reinterpret_cast<const float2*>(obs + grow * 10);
                #pragma unroll
                for (int f = 0; f < 5; f++) {
                    float2 v = q[f];
                    od[2 * f]     = dup2(v.x);
                    od[2 * f + 1] = dup2(v.y);
                }
            } else {
                #pragma unroll
                for (int f = 0; f < 10; f++) od[f] = 0ull;
            }
            const u32 swr = ((u32)(prow & 7)) << 4;
            #pragma unroll 1
            for (int blk = 0; blk < 4; blk++) {
                u32 xq[4];
                #pragma unroll
                for (int q = 0; q < 4; q++) {
                    const int jp = jq * 16 + blk * 4 + q;
                    const ulonglong2* wv =
                        reinterpret_cast<const ulonglong2*>(w1p + jp * 10);
                    ulonglong2 w01 = wv[0], w23 = wv[1], w45 = wv[2],
                               w67 = wv[3], w89 = wv[4];
                    u64 z = b1p[jp];
                    z = fma2(od[0], w01.x, z); z = fma2(od[1], w01.y, z);
                    z = fma2(od[2], w23.x, z); z = fma2(od[3], w23.y, z);
                    z = fma2(od[4], w45.x, z); z = fma2(od[5], w45.y, z);
                    z = fma2(od[6], w67.x, z); z = fma2(od[7], w67.y, z);
                    z = fma2(od[8], w89.x, z); z = fma2(od[9], w89.y, z);
                    float z0, z1; upk2(z, z0, z1);
                    xq[q] = cvt_f16x2(fast_silu(z1), fast_silu(z0));
                }
                const u32 kb  = (u32)(jq * 64 + blk * 16);
                const u32 off = (u32)prow * 256 + (kb ^ swr);
                *reinterpret_cast<uint4*>(smc + SM_XF + off) =
                    make_uint4(xq[0], xq[1], xq[2], xq[3]);
            }
        }
        __syncthreads();

        // ======================= MMA: warps 0-7, 32r x 32c, 2 passes ===============
        if (wid < 8) {
            float acc[2][4][4];
            #pragma unroll
            for (int m = 0; m < 2; m++)
                #pragma unroll
                for (int nt = 0; nt < 4; nt++)
                    #pragma unroll
                    for (int c = 0; c < 4; c++) acc[m][nt][c] = 0.f;

            #pragma unroll 1
            for (int ks = 0; ks < 8; ks++) {
                const u32 kbyte = (u32)(32 * ks);
                const u32 ka = (kbyte + a_koff) ^ swz;
                const u32 kb = (kbyte + b_koff) ^ swz;
                u32 a0[4], a1[4], bf0[4], bf1[4];
                ldsm4(a0, aF0 + ka);
                ldsm4(a1, aF1 + ka);
                // pass 1: A x B-hi
                ldsm4(bf0, bHb[0] + kb);
                ldsm4(bf1, bHb[1] + kb);
                #pragma unroll
                for (int nt = 0; nt < 4; nt++) {
                    u32 b0 = (nt < 2 ? bf0 : bf1)[(nt & 1) * 2];
                    u32 b1v = (nt < 2 ? bf0 : bf1)[(nt & 1) * 2 + 1];
                    mma_f16(acc[0][nt], a0, b0, b1v);
                    mma_f16(acc[1][nt], a1, b0, b1v);
                }
                // pass 2: A x B-lo
                ldsm4(bf0, bLb[0] + kb);
                ldsm4(bf1, bLb[1] + kb);
                #pragma unroll
                for (int nt = 0; nt < 4; nt++) {
                    u32 b0 = (nt < 2 ? bf0 : bf1)[(nt & 1) * 2];
                    u32 b1v = (nt < 2 ? bf0 : bf1)[(nt & 1) * 2 + 1];
                    mma_f16(acc[0][nt], a0, b0, b1v);
                    mma_f16(acc[1][nt], a1, b0, b1v);
                }
            }

            // ---- heads partials: 4 rows/lane, quad-reduce, tig-select write ----
            float p0[4] = {0.f, 0.f, 0.f, 0.f};
            float p1[4] = {0.f, 0.f, 0.f, 0.f};
            #pragma unroll
            for (int m = 0; m < 2; m++)
                #pragma unroll
                for (int nt = 0; nt < 4; nt++)
                    #pragma unroll
                    for (int c = 0; c < 2; c++) {
                        const int col = nh * 32 + nt * 8 + 2 * tig + c;
                        const float bias = b2f[col];
                        const float vlo = fast_silu(acc[m][nt][c] + bias);
                        const float vhi = fast_silu(acc[m][nt][2 + c] + bias);
                        if (nh == 0) {
                            const float wA = w31f[col], wB = w31f[32 + col];
                            p0[2 * m]     += vlo * wA; p1[2 * m]     += vlo * wB;
                            p0[2 * m + 1] += vhi * wA; p1[2 * m + 1] += vhi * wB;
                        } else {
                            const float wC = w32f[col - 32];
                            p0[2 * m]     += vlo * wC;
                            p0[2 * m + 1] += vhi * wC;
                        }
                    }
            #pragma unroll
            for (int i = 0; i < 4; i++) {
                p0[i] += __shfl_xor_sync(0xFFFFFFFFu, p0[i], 1);
                p0[i] += __shfl_xor_sync(0xFFFFFFFFu, p0[i], 2);
                if (nh == 0) {
                    p1[i] += __shfl_xor_sync(0xFFFFFFFFu, p1[i], 1);
                    p1[i] += __shfl_xor_sync(0xFFFFFFFFu, p1[i], 2);
                }
            }
            {
                const int row = mg * 32 + gid + tig * 8;
                const float s0 = (tig == 0) ? p0[0] : (tig == 1) ? p0[1]
                               : (tig == 2) ? p0[2] : p0[3];
                if (nh == 0) {
                    const float s1 = (tig == 0) ? p1[0] : (tig == 1) ? p1[1]
                                   : (tig == 2) ? p1[2] : p1[3];
                    u01[row] = make_float2(s0, s1);
                } else {
                    awb[row] = s0;
                }
            }
        }
        __syncthreads();

        // ======================= CBF + store (warps 8-11) =======================
        if (tid >= 256 && tid < 384) {
            const int r = tid - 256;
            const long long grow = row_base + ph * 128 + r;
            if (grow < B) {
                float2 uv = u01[r];
                const float u0 = uv.x + scal[0];
                const float u1 = uv.y + scal[1];
                const float aw = awb[r] + scal[2];
                const float2* pp = reinterpret_cast<const float2*>(obs + grow * 10 + 6);
                const float2 rv = pp[0], vv = pp[1];
                const float alpha   = 4.0f * fast_sigmoid(aw);
                const float barrier = rv.x * rv.x + rv.y * rv.y - 0.64f;
                const float lf      = -2.0f * (rv.x * vv.x + rv.y * vv.y);
                const float Gx = -2.0f * rv.x, Gy = -2.0f * rv.y;
                const float hh   = lf + alpha * barrier;
                const float gg   = Gx * Gx + Gy * Gy;
                const float viol = Gx * u0 + Gy * u1 - hh;
                const float lam  = (gg > 0.0f)
                    ? __fdividef(fmaxf(viol, 0.0f), fmaxf(gg, 1e-12f))
                    : 0.0f;
                reinterpret_cast<float2*>(out)[grow] =
                    make_float2(u0 - lam * Gx, u1 - lam * Gy);
            }
        }
    }
}

extern "C" void kernel_launch(void* const* d_in, const int* in_sizes, int n_in,
                              void* d_out, int out_size)
{
    const float* obs = (const float*)d_in[0];
    const float* W1  = (const float*)d_in[1];
    const float* b1  = (const float*)d_in[2];
    const float* W21 = (const float*)d_in[3];
    const float* b21 = (const float*)d_in[4];
    const float* W22 = (const float*)d_in[5];
    const float* b22 = (const float*)d_in[6];
    const float* W31 = (const float*)d_in[7];
    const float* b31 = (const float*)d_in[8];
    const float* W32 = (const float*)d_in[9];
    const float* b32 = (const float*)d_in[10];
    float* out = (float*)d_out;

    int B = in_sizes[0] / 10;

    cudaFuncSetAttribute(barriernet_kernel,
                         cudaFuncAttributeMaxDynamicSharedMemorySize, SMEM_BYTES);

    int blocks = (B + 511) / 512;
    barriernet_kernel<<<blocks, 512, SMEM_BYTES>>>(
        obs, W1, b1, W21, b21, W22, b22, W31, b31, W32, b32, out, B);
}

// round 13
// speedup vs baseline: 1.4579x; 1.2414x over previous
#include <cuda_runtime.h>
#include <cuda_fp16.h>
#include <cstdint>

// ---------------------------------------------------------------------------
// BarrierNet — mma.sync fp16 single-pass, tanh-silu, v13.
//   CTA = 512 threads, 512 rows, four 128-row phases. 2 CTAs/SM.
//   Phase A : layer1 fp32 FFMA2, tanh-silu (1 MUFU), cvt fp16x2, STS swizzled.
//   MMA     : warps 0-7, 32r x 32c tiles, SINGLE pass A*B fp16, fp32 acc.
//   Heads   : partials in MMA warps, quad shfl-reduce, tig-select write.
//   CBF     : warps 8-11 after the barrier.
// ---------------------------------------------------------------------------

typedef unsigned long long u64;
typedef unsigned int u32;

#define SM_XF    0        // fp16 x [128 rows][128 k]  32768
#define SM_WF    32768    // fp16 W2 [64 n][128 k]     16384
#define SM_W1P   49152    // u64[640]  W1 (j,j+1) pairs 5120
#define SM_B1P   54272    // u64[64]   512
#define SM_B2    54784    // f32[64]   256
#define SM_W31   55040    // f32[64]   256
#define SM_W32   55296    // f32[32]   128
#define SM_SCAL  55424    // f32[4]    16
#define SM_U01   55440    // float2[128] 1024
#define SM_AW    56464    // f32[128]    512
#define SMEM_BYTES 56976

static __device__ __forceinline__ u32 smem_u32(const void* p) {
    u32 a;
    asm("{ .reg .u64 t; cvta.to.shared.u64 t, %1; cvt.u32.u64 %0, t; }"
        : "=r"(a) : "l"(p));
    return a;
}
static __device__ __forceinline__ u64 pk2(float lo, float hi) {
    u64 r; asm("mov.b64 %0, {%1, %2};" : "=l"(r) : "f"(lo), "f"(hi)); return r;
}
static __device__ __forceinline__ void upk2(u64 v, float& lo, float& hi) {
    asm("mov.b64 {%0, %1}, %2;" : "=f"(lo), "=f"(hi) : "l"(v));
}
static __device__ __forceinline__ u64 fma2(u64 a, u64 b, u64 c) {
    u64 d; asm("fma.rn.f32x2 %0, %1, %2, %3;" : "=l"(d) : "l"(a), "l"(b), "l"(c)); return d;
}
static __device__ __forceinline__ u64 dup2(float w) { return pk2(w, w); }

static __device__ __forceinline__ float tanh_ap(float x) {
    float t; asm("tanh.approx.f32 %0, %1;" : "=f"(t) : "f"(x)); return t;
}
// silu(z) = 0.5*z*(1 + tanh(z/2)) : 1 MUFU
static __device__ __forceinline__ float fast_silu(float z) {
    return 0.5f * z * (1.0f + tanh_ap(0.5f * z));
}
// sigmoid(z) = 0.5*(1 + tanh(z/2)) : 1 MUFU
static __device__ __forceinline__ float fast_sigmoid(float z) {
    return 0.5f * (1.0f + tanh_ap(0.5f * z));
}
// pack two floats to fp16x2 (lower 16 bits = s0)
static __device__ __forceinline__ u32 cvt_f16x2(float s1, float s0) {
    u32 d; asm("cvt.rn.f16x2.f32 %0, %1, %2;" : "=r"(d) : "f"(s1), "f"(s0));
    return d;
}
static __device__ __forceinline__ void ldsm4(u32* r, u32 addr) {
    asm volatile("ldmatrix.sync.aligned.m8n8.x4.shared.b16 {%0,%1,%2,%3}, [%4];"
        : "=r"(r[0]), "=r"(r[1]), "=r"(r[2]), "=r"(r[3]) : "r"(addr));
}
static __device__ __forceinline__ void mma_f16(float* d, const u32* a, u32 b0, u32 b1) {
    asm volatile("mma.sync.aligned.m16n8k16.row.col.f32.f16.f16.f32 "
        "{%0,%1,%2,%3}, {%4,%5,%6,%7}, {%8,%9}, {%0,%1,%2,%3};"
        : "+f"(d[0]), "+f"(d[1]), "+f"(d[2]), "+f"(d[3])
        : "r"(a[0]), "r"(a[1]), "r"(a[2]), "r"(a[3]), "r"(b0), "r"(b1));
}

__global__ void __launch_bounds__(512, 2)
barriernet_kernel(const float* __restrict__ obs,
                  const float* __restrict__ W1,  const float* __restrict__ b1,
                  const float* __restrict__ W21, const float* __restrict__ b21,
                  const float* __restrict__ W22, const float* __restrict__ b22,
                  const float* __restrict__ W31, const float* __restrict__ b31,
                  const float* __restrict__ W32, const float* __restrict__ b32,
                  float* __restrict__ out, int B)
{
    extern __shared__ char smc[];
    const u32 smb = smem_u32(smc);
    const int tid = threadIdx.x;

    u64*    w1p  = reinterpret_cast<u64*>(smc + SM_W1P);
    u64*    b1p  = reinterpret_cast<u64*>(smc + SM_B1P);
    float*  b2f  = reinterpret_cast<float*>(smc + SM_B2);
    float*  w31f = reinterpret_cast<float*>(smc + SM_W31);
    float*  w32f = reinterpret_cast<float*>(smc + SM_W32);
    float*  scal = reinterpret_cast<float*>(smc + SM_SCAL);
    float2* u01  = reinterpret_cast<float2*>(smc + SM_U01);
    float*  awb  = reinterpret_cast<float*>(smc + SM_AW);

    // ------------------------------ staging ------------------------------
    for (int i = tid; i < 640; i += 512) {
        int jp = i / 10, f = i - jp * 10;
        w1p[i] = pk2(W1[(2 * jp) * 10 + f], W1[(2 * jp + 1) * 10 + f]);
    }
    if (tid < 64) {
        b1p[tid]  = pk2(b1[2 * tid], b1[2 * tid + 1]);
        b2f[tid]  = (tid < 32) ? b21[tid] : b22[tid - 32];
        w31f[tid] = W31[tid];                       // [2][32] row-major
    }
    if (tid < 32) w32f[tid] = W32[tid];
    if (tid == 0) { scal[0] = b31[0]; scal[1] = b31[1]; scal[2] = b32[0]; }

    // W2 = [W21 ; W22] fp16, [n][k] 256B rows, XOR swizzle
    for (int i = tid; i < 4096; i += 512) {
        int n = i >> 6, kp = i & 63;                // elems k = 2kp, 2kp+1
        const float* src = (n < 32) ? (W21 + n * 128 + 2 * kp)
                                    : (W22 + (n - 32) * 128 + 2 * kp);
        float2 w = *reinterpret_cast<const float2*>(src);
        u32 off = (u32)(n * 256) + (((u32)(4 * kp)) ^ ((u32)(n & 7) << 4));
        *reinterpret_cast<u32*>(smc + SM_WF + off) = cvt_f16x2(w.y, w.x);
    }
    __syncthreads();

    const long long row_base = (long long)blockIdx.x * 512;

    // -------- phase-A mapping --------
    const int prow = tid & 127;
    const int jq   = tid >> 7;          // 16 j-pairs starting at jq*16

    // -------- mma mapping (warps 0-7): 32 rows x 32 cols --------
    const int wid = tid >> 5, lane = tid & 31;
    const int gid = lane >> 2, tig = lane & 3;
    const int g8  = lane >> 3, r8 = lane & 7;
    const int mg  = wid & 3;            // rows mg*32 .. mg*32+31
    const int nh  = wid >> 2;           // n-half (0: u cols, 1: alpha cols)
    const u32 swz    = (u32)r8 << 4;
    const u32 a_koff = (u32)((g8 >> 1) << 4);
    const int arow0  = mg * 32 + ((g8 & 1) << 3) + r8;
    const u32 aF0 = smb + SM_XF + (u32)arow0 * 256;
    const u32 aF1 = aF0 + 16 * 256;
    const u32 b_noff = (u32)(((g8 >> 1) << 3) + r8);
    const u32 b_koff = (u32)((g8 & 1) << 4);
    u32 bFb[2];
    #pragma unroll
    for (int g = 0; g < 2; g++) {
        u32 n = (u32)(nh * 32 + g * 16) + b_noff;
        bFb[g] = smb + SM_WF + n * 256;
    }

    #pragma unroll 1
    for (int ph = 0; ph < 4; ph++) {
        // ======================= Phase A (128 rows, all warps) =======================
        {
            const long long grow = row_base + ph * 128 + prow;
            u64 od[10];
            if (grow < B) {
                const float2* q = reinterpret_cast<const float2*>(obs + grow * 10);
                #pragma unroll
                for (int f = 0; f < 5; f++) {
                    float2 v = q[f];
                    od[2 * f]     = dup2(v.x);
                    od[2 * f + 1] = dup2(v.y);
                }
            } else {
                #pragma unroll
                for (int f = 0; f < 10; f++) od[f] = 0ull;
            }
            const u32 swr = ((u32)(prow & 7)) << 4;
            #pragma unroll 1
            for (int blk = 0; blk < 4; blk++) {
                u32 xq[4];
                #pragma unroll
                for (int q = 0; q < 4; q++) {
                    const int jp = jq * 16 + blk * 4 + q;
                    const ulonglong2* wv =
                        reinterpret_cast<const ulonglong2*>(w1p + jp * 10);
                    ulonglong2 w01 = wv[0], w23 = wv[1], w45 = wv[2],
                               w67 = wv[3], w89 = wv[4];
                    u64 z = b1p[jp];
                    z = fma2(od[0], w01.x, z); z = fma2(od[1], w01.y, z);
                    z = fma2(od[2], w23.x, z); z = fma2(od[3], w23.y, z);
                    z = fma2(od[4], w45.x, z); z = fma2(od[5], w45.y, z);
                    z = fma2(od[6], w67.x, z); z = fma2(od[7], w67.y, z);
                    z = fma2(od[8], w89.x, z); z = fma2(od[9], w89.y, z);
                    float z0, z1; upk2(z, z0, z1);
                    xq[q] = cvt_f16x2(fast_silu(z1), fast_silu(z0));
                }
                const u32 kb  = (u32)(jq * 64 + blk * 16);
                const u32 off = (u32)prow * 256 + (kb ^ swr);
                *reinterpret_cast<uint4*>(smc + SM_XF + off) =
                    make_uint4(xq[0], xq[1], xq[2], xq[3]);
            }
        }
        __syncthreads();

        // ======================= MMA: warps 0-7, 32r x 32c, single pass ===========
        if (wid < 8) {
            float acc[2][4][4];
            #pragma unroll
            for (int m = 0; m < 2; m++)
                #pragma unroll
                for (int nt = 0; nt < 4; nt++)
                    #pragma unroll
                    for (int c = 0; c < 4; c++) acc[m][nt][c] = 0.f;

            #pragma unroll 2
            for (int ks = 0; ks < 8; ks++) {
                const u32 kbyte = (u32)(32 * ks);
                const u32 ka = (kbyte + a_koff) ^ swz;
                const u32 kb = (kbyte + b_koff) ^ swz;
                u32 a0[4], a1[4], bf0[4], bf1[4];
                ldsm4(a0, aF0 + ka);
                ldsm4(a1, aF1 + ka);
                ldsm4(bf0, bFb[0] + kb);
                ldsm4(bf1, bFb[1] + kb);
                #pragma unroll
                for (int nt = 0; nt < 4; nt++) {
                    u32 b0 = (nt < 2 ? bf0 : bf1)[(nt & 1) * 2];
                    u32 b1v = (nt < 2 ? bf0 : bf1)[(nt & 1) * 2 + 1];
                    mma_f16(acc[0][nt], a0, b0, b1v);
                    mma_f16(acc[1][nt], a1, b0, b1v);
                }
            }

            // ---- heads partials: 4 rows/lane, quad-reduce, tig-select write ----
            float p0[4] = {0.f, 0.f, 0.f, 0.f};
            float p1[4] = {0.f, 0.f, 0.f, 0.f};
            #pragma unroll
            for (int m = 0; m < 2; m++)
                #pragma unroll
                for (int nt = 0; nt < 4; nt++)
                    #pragma unroll
                    for (int c = 0; c < 2; c++) {
                        const int col = nh * 32 + nt * 8 + 2 * tig + c;
                        const float bias = b2f[col];
                        const float vlo = fast_silu(acc[m][nt][c] + bias);
                        const float vhi = fast_silu(acc[m][nt][2 + c] + bias);
                        if (nh == 0) {
                            const float wA = w31f[col], wB = w31f[32 + col];
                            p0[2 * m]     += vlo * wA; p1[2 * m]     += vlo * wB;
                            p0[2 * m + 1] += vhi * wA; p1[2 * m + 1] += vhi * wB;
                        } else {
                            const float wC = w32f[col - 32];
                            p0[2 * m]     += vlo * wC;
                            p0[2 * m + 1] += vhi * wC;
                        }
                    }
            #pragma unroll
            for (int i = 0; i < 4; i++) {
                p0[i] += __shfl_xor_sync(0xFFFFFFFFu, p0[i], 1);
                p0[i] += __shfl_xor_sync(0xFFFFFFFFu, p0[i], 2);
                if (nh == 0) {
                    p1[i] += __shfl_xor_sync(0xFFFFFFFFu, p1[i], 1);
                    p1[i] += __shfl_xor_sync(0xFFFFFFFFu, p1[i], 2);
                }
            }
            {
                const int row = mg * 32 + gid + tig * 8;
                const float s0 = (tig == 0) ? p0[0] : (tig == 1) ? p0[1]
                               : (tig == 2) ? p0[2] : p0[3];
                if (nh == 0) {
                    const float s1 = (tig == 0) ? p1[0] : (tig == 1) ? p1[1]
                                   : (tig == 2) ? p1[2] : p1[3];
                    u01[row] = make_float2(s0, s1);
                } else {
                    awb[row] = s0;
                }
            }
        }
        __syncthreads();

        // ======================= CBF + store (warps 8-11) =======================
        if (tid >= 256 && tid < 384) {
            const int r = tid - 256;
            const long long grow = row_base + ph * 128 + r;
            if (grow < B) {
                float2 uv = u01[r];
                const float u0 = uv.x + scal[0];
                const float u1 = uv.y + scal[1];
                const float aw = awb[r] + scal[2];
                const float2* pp = reinterpret_cast<const float2*>(obs + grow * 10 + 6);
                const float2 rv = pp[0], vv = pp[1];
                const float alpha   = 4.0f * fast_sigmoid(aw);
                const float barrier = rv.x * rv.x + rv.y * rv.y - 0.64f;
                const float lf      = -2.0f * (rv.x * vv.x + rv.y * vv.y);
                const float Gx = -2.0f * rv.x, Gy = -2.0f * rv.y;
                const float hh   = lf + alpha * barrier;
                const float gg   = Gx * Gx + Gy * Gy;
                const float viol = Gx * u0 + Gy * u1 - hh;
                const float lam  = (gg > 0.0f)
                    ? __fdividef(fmaxf(viol, 0.0f), fmaxf(gg, 1e-12f))
                    : 0.0f;
                reinterpret_cast<float2*>(out)[grow] =
                    make_float2(u0 - lam * Gx, u1 - lam * Gy);
            }
        }
    }
}

extern "C" void kernel_launch(void* const* d_in, const int* in_sizes, int n_in,
                              void* d_out, int out_size)
{
    const float* obs = (const float*)d_in[0];
    const float* W1  = (const float*)d_in[1];
    const float* b1  = (const float*)d_in[2];
    const float* W21 = (const float*)d_in[3];
    const float* b21 = (const float*)d_in[4];
    const float* W22 = (const float*)d_in[5];
    const float* b22 = (const float*)d_in[6];
    const float* W31 = (const float*)d_in[7];
    const float* b31 = (const float*)d_in[8];
    const float* W32 = (const float*)d_in[9];
    const float* b32 = (const float*)d_in[10];
    float* out = (float*)d_out;

    int B = in_sizes[0] / 10;

    cudaFuncSetAttribute(barriernet_kernel,
                         cudaFuncAttributeMaxDynamicSharedMemorySize, SMEM_BYTES);

    int blocks = (B + 511) / 512;
    barriernet_kernel<<<blocks, 512, SMEM_BYTES>>>(
        obs, W1, b1, W21, b21, W22, b22, W31, b31, W32, b32, out, B);
}